// round 3
// baseline (speedup 1.0000x reference)
#include <cuda_runtime.h>
#include <math.h>

#define IMG    64
#define NSLICE 16
#define NCOIL  4
#define NSING  4
#define NECHO  3
#define NRO    32
#define NPT    96
#define NEC    (NECHO * NCOIL)   // 12
#define NPIX   (IMG * IMG)       // 4096

typedef unsigned long long u64;

// ---- packed f32x2 helpers (FFMA2: 2x fp32 throughput on sm_103a) ----------
__device__ __forceinline__ u64 pack2(float lo, float hi) {
    u64 r;
    asm("mov.b64 %0, {%1, %2};" : "=l"(r)
        : "r"(__float_as_uint(lo)), "r"(__float_as_uint(hi)));
    return r;
}
__device__ __forceinline__ u64 dup2(float v) { return pack2(v, v); }
__device__ __forceinline__ void fma2(u64& d, u64 a, u64 b) {
    asm("fma.rn.f32x2 %0, %1, %2, %3;" : "=l"(d) : "l"(a), "l"(b), "l"(d));
}
__device__ __forceinline__ float2 unpack2(u64 v) {
    unsigned lo, hi;
    asm("mov.b64 {%0, %1}, %2;" : "=r"(lo), "=r"(hi) : "l"(v));
    return make_float2(__uint_as_float(lo), __uint_as_float(hi));
}

// scf[kz][c][j=n*3+e][pix]  (25 MB)
__device__ float2 g_scf[NSLICE * NCOIL * (NSING * NECHO) * NPIX];
// imgW[r][ec=e*4+c][pix]    (12.6 MB)
__device__ float2 g_imgW[NRO * NEC * NPIX];
// phase tables [r][x][p], [r][y][p]
__device__ float2 g_ex[NRO * IMG * NPT];
__device__ float2 g_ey[NRO * IMG * NPT];

// ---------------------------------------------------------------------------
// Stage A: z-DFT (all 16 kz) of sign(z)*singulars*smap, per (pix, c, n).
// Packed-FFMA2 accumulators. grid (16 pixblocks, 16 = c*4+n), block 256.
// ---------------------------------------------------------------------------
__global__ __launch_bounds__(256, 2)
void stageA_kernel(const float* __restrict__ singulars,   // [64,64,16,4,3,2]
                   const float* __restrict__ smap)        // [4,64,64,16,2]
{
    const int pix = blockIdx.x * 256 + threadIdx.x;
    const int cn  = blockIdx.y;
    const int c   = cn >> 2;
    const int n   = cn & 3;
    const int x   = pix & (IMG - 1);
    const int y   = pix >> 6;

    // packed twiddles, sign(z) folded:
    // sW1[kz][z] = (w.x, w.y), sW2[kz][z] = (-w.y, w.x)
    __shared__ u64 sW1[NSLICE * NSLICE];
    __shared__ u64 sW2[NSLICE * NSLICE];
    {
        int kz = threadIdx.x >> 4, z = threadIdx.x & 15;
        float ang = -(2.0f * (float)M_PI / (float)NSLICE) * (float)(kz * z);
        float s, co; sincosf(ang, &s, &co);
        float sgn = (z & 1) ? -1.0f : 1.0f;
        co *= sgn; s *= sgn;
        sW1[threadIdx.x] = pack2(co, s);
        sW2[threadIdx.x] = pack2(-s, co);
    }
    __syncthreads();

    const float* vbase = singulars + ((size_t)(x * IMG + y) * NSLICE) * (NSING * NECHO * 2) + n * 6;
    const float* sbase = smap + ((size_t)(c * NPIX + x * IMG + y) * NSLICE) * 2;

    u64 acc[NSLICE][NECHO];
#pragma unroll
    for (int kz = 0; kz < NSLICE; ++kz)
#pragma unroll
        for (int e = 0; e < NECHO; ++e) acc[kz][e] = 0ull;

    for (int z = 0; z < NSLICE; ++z) {
        float2 sm = *(const float2*)(sbase + z * 2);
        const float* v = vbase + z * (NSING * NECHO * 2);
        float2 v0 = *(const float2*)(v + 0);
        float2 v1 = *(const float2*)(v + 2);
        float2 v2 = *(const float2*)(v + 4);

        u64 dR[3], dI[3];
        dR[0] = dup2(v0.x * sm.x - v0.y * sm.y); dI[0] = dup2(v0.x * sm.y + v0.y * sm.x);
        dR[1] = dup2(v1.x * sm.x - v1.y * sm.y); dI[1] = dup2(v1.x * sm.y + v1.y * sm.x);
        dR[2] = dup2(v2.x * sm.x - v2.y * sm.y); dI[2] = dup2(v2.x * sm.y + v2.y * sm.x);

#pragma unroll
        for (int kz = 0; kz < NSLICE; ++kz) {
            u64 w1 = sW1[kz * NSLICE + z];
            u64 w2 = sW2[kz * NSLICE + z];
#pragma unroll
            for (int e = 0; e < NECHO; ++e) {
                fma2(acc[kz][e], dR[e], w1);
                fma2(acc[kz][e], dI[e], w2);
            }
        }
    }

#pragma unroll
    for (int kz = 0; kz < NSLICE; ++kz)
#pragma unroll
        for (int e = 0; e < NECHO; ++e) {
            g_scf[((size_t)(kz * NCOIL + c) * (NSING * NECHO) + n * NECHO + e) * NPIX + pix]
                = unpack2(acc[kz][e]);
        }
}

// ---------------------------------------------------------------------------
// Stage B: mix with Ur, gather slice bin: imgW[r][e*4+c][pix]
// ---------------------------------------------------------------------------
__global__ __launch_bounds__(256)
void stageB_kernel(const float* __restrict__ ur_list,   // [1,32,4]
                   const int*   __restrict__ sbin)      // [32]
{
    const int pix = blockIdx.x * 256 + threadIdx.x;
    const int r   = blockIdx.y;
    const int kzr = sbin[r];

    float u[NSING];
#pragma unroll
    for (int n = 0; n < NSING; ++n) u[n] = ur_list[r * NSING + n];

    const float2* base = g_scf + (size_t)(kzr * NCOIL) * (NSING * NECHO) * NPIX;

#pragma unroll
    for (int e = 0; e < NECHO; ++e) {
#pragma unroll
        for (int c = 0; c < NCOIL; ++c) {
            float ar = 0.f, ai = 0.f;
#pragma unroll
            for (int n = 0; n < NSING; ++n) {
                float2 s = base[((size_t)c * (NSING * NECHO) + n * NECHO + e) * NPIX + pix];
                ar = fmaf(u[n], s.x, ar);
                ai = fmaf(u[n], s.y, ai);
            }
            g_imgW[((size_t)r * NEC + e * NCOIL + c) * NPIX + pix] = make_float2(ar, ai);
        }
    }
}

// ---------------------------------------------------------------------------
// Phase tables: g_ex[r][x][p] = exp(-i*w0*(x-32)), g_ey[r][y][p] = exp(-i*w1*(y-32))
// ---------------------------------------------------------------------------
__global__ __launch_bounds__(96)
void exgen_kernel(const float* __restrict__ ktraj)   // [1,32,96,2]
{
    const int r = blockIdx.x;
    const int p = threadIdx.x;
    const float w0 = ktraj[(r * NPT + p) * 2 + 0];
    const float w1 = ktraj[(r * NPT + p) * 2 + 1];

    {
        float sx, cx; sincosf(w0, &sx, &cx);
        float pr, pi; sincosf(32.0f * w0, &pi, &pr);
        for (int x = 0; x < IMG; ++x) {
            g_ex[(r * IMG + x) * NPT + p] = make_float2(pr, pi);
            float t = pr;
            pr = fmaf(pr, cx, pi * sx);
            pi = fmaf(pi, cx, -(t * sx));
        }
    }
    {
        float sy, cy; sincosf(w1, &sy, &cy);
        float pr, pi; sincosf(32.0f * w1, &pi, &pr);
        for (int y = 0; y < IMG; ++y) {
            g_ey[(r * IMG + y) * NPT + p] = make_float2(pr, pi);
            float t = pr;
            pr = fmaf(pr, cy, pi * sy);
            pi = fmaf(pi, cy, -(t * sy));
        }
    }
}

// ---------------------------------------------------------------------------
// NUFFT: packed-FFMA2 register-tiled complex GEMM, split over p halves.
// grid (32 r, 12 ec, 2 p-half), block 192.  Thread tile: 4p x 4y.
// x-dim processed in 2 smem phases of 32 to keep smem at ~29KB (5 blocks/SM).
// ---------------------------------------------------------------------------
#define TS      66    // padded y-stride for transposed image tile
#define XPH     32    // x per smem phase
#define PBLK    48    // points per block

__global__ __launch_bounds__(192, 5)
void nufft_kernel(float2* __restrict__ out)   // [96,4,32,3] complex
{
    extern __shared__ float2 sh[];
    float2* sT  = sh;                 // [32][TS]  : sT[xl][y]
    float2* sEx = sh + XPH * TS;      // [32][48]  : sEx[xl][pl]

    const int r   = blockIdx.x;
    const int ec  = blockIdx.y;
    const int ph  = blockIdx.z;       // p half
    const int tid = threadIdx.x;

    const int tx = tid % 12;          // p-tile (4 points)
    const int ty = tid / 12;          // y-tile (4 rows)
    const int p0 = tx * 4;            // local point base
    const int y0 = ty * 4;

    const float2* gimg = g_imgW + (size_t)(r * NEC + ec) * NPIX;
    const float2* gex  = g_ex + (size_t)r * IMG * NPT + ph * PBLK;

    u64 acc[4][4];
#pragma unroll
    for (int a = 0; a < 4; ++a)
#pragma unroll
        for (int b = 0; b < 4; ++b) acc[a][b] = 0ull;

    for (int xb = 0; xb < IMG; xb += XPH) {
        if (xb) __syncthreads();

        // load + transpose image slab: sT[xl][y] = img[y][xb+xl]
        for (int i = tid; i < XPH * IMG; i += 192) {
            int xl = i & (XPH - 1), y = i >> 5;
            sT[xl * TS + y] = gimg[y * IMG + xb + xl];
        }
        // load ex slab for this p half
        for (int i = tid; i < XPH * PBLK; i += 192) {
            int xl = i / PBLK, pl = i % PBLK;
            sEx[i] = gex[(xb + xl) * NPT + pl];
        }
        __syncthreads();

#pragma unroll 4
        for (int xl = 0; xl < XPH; ++xl) {
            const float4* pe = reinterpret_cast<const float4*>(&sEx[xl * PBLK + p0]);
            float4 e01 = pe[0], e23 = pe[1];
            const float4* pi4 = reinterpret_cast<const float4*>(&sT[xl * TS + y0]);
            float4 i01 = pi4[0], i23 = pi4[1];

            u64 ep[4] = { pack2(e01.x, e01.y),  pack2(e01.z, e01.w),
                          pack2(e23.x, e23.y),  pack2(e23.z, e23.w) };
            u64 er[4] = { pack2(-e01.y, e01.x), pack2(-e01.w, e01.z),
                          pack2(-e23.y, e23.x), pack2(-e23.w, e23.z) };

            float ivx[4] = { i01.x, i01.z, i23.x, i23.z };
            float ivy[4] = { i01.y, i01.w, i23.y, i23.w };

#pragma unroll
            for (int yy = 0; yy < 4; ++yy) {
                u64 dx = dup2(ivx[yy]);
                u64 dy = dup2(ivy[yy]);
#pragma unroll
                for (int pp = 0; pp < 4; ++pp) {
                    fma2(acc[pp][yy], dx, ep[pp]);
                    fma2(acc[pp][yy], dy, er[pp]);
                }
            }
        }
    }

    __syncthreads();                  // done with sEx; reuse as reduction buffer
    float2* sRed = sEx;               // [48][16]

    const float2* gey = g_ey + (size_t)r * IMG * NPT + ph * PBLK;
#pragma unroll
    for (int pp = 0; pp < 4; ++pp) {
        float outr = 0.f, outi = 0.f;
#pragma unroll
        for (int yy = 0; yy < 4; ++yy) {
            float2 t  = unpack2(acc[pp][yy]);
            float2 ey = gey[(y0 + yy) * NPT + p0 + pp];
            outr = fmaf(t.x,  ey.x, outr);
            outr = fmaf(-t.y, ey.y, outr);
            outi = fmaf(t.x,  ey.y, outi);
            outi = fmaf(t.y,  ey.x, outi);
        }
        sRed[(p0 + pp) * 16 + ty] = make_float2(outr, outi);
    }
    __syncthreads();

    if (tid < PBLK) {
        float sr = 0.f, si = 0.f;
#pragma unroll
        for (int k = 0; k < 16; ++k) {
            float2 v = sRed[tid * 16 + k];
            sr += v.x; si += v.y;
        }
        const int p = ph * PBLK + tid;
        const int e = ec >> 2;
        const int c = ec & 3;
        out[((p * NCOIL + c) * NRO + r) * NECHO + e] = make_float2(sr, si);
    }
}

// ---------------------------------------------------------------------------
extern "C" void kernel_launch(void* const* d_in, const int* in_sizes, int n_in,
                              void* d_out, int out_size)
{
    const float* singulars = (const float*)d_in[0];
    const float* smap      = (const float*)d_in[1];
    const float* ktraj     = (const float*)d_in[2];
    const float* ur_list   = (const float*)d_in[3];
    const int*   sbin      = (const int*)d_in[4];
    // d_in[5] = dc (unused by the forward reference)

    float2* out = (float2*)d_out;

    const int smemNufft = (XPH * TS + XPH * PBLK) * (int)sizeof(float2); // ~29KB
    cudaFuncSetAttribute(nufft_kernel, cudaFuncAttributeMaxDynamicSharedMemorySize, smemNufft);

    stageA_kernel<<<dim3(NPIX / 256, 16), 256>>>(singulars, smap);
    stageB_kernel<<<dim3(NPIX / 256, NRO), 256>>>(ur_list, sbin);
    exgen_kernel<<<NRO, NPT>>>(ktraj);
    nufft_kernel<<<dim3(NRO, NEC, 2), 192, smemNufft>>>(out);
}